// round 16
// baseline (speedup 1.0000x reference)
#include <cuda_runtime.h>

#define BB 2048
#define TT 1024
#define DD 64
#define HH 16
#define CH 256             // timesteps per K1 warp (4 warps per batch)
#define WU 96              // warmup steps: decay exp(-96/6) ~ 1.1e-7
#define INV_TAU (1.0f/6.0f)

typedef unsigned long long u64;

// xw scratch: [B, T, 16]
__device__ float g_xw[(size_t)BB * TT * HH];

__device__ __forceinline__ u64 pk2(float lo, float hi) {
    u64 r; asm("mov.b64 %0, {%1,%2};" : "=l"(r) : "f"(lo), "f"(hi)); return r;
}
__device__ __forceinline__ void unpk2(u64 a, float& lo, float& hi) {
    asm("mov.b64 {%0,%1}, %2;" : "=f"(lo), "=f"(hi) : "l"(a));
}
__device__ __forceinline__ u64 mul2(u64 a, u64 b) {
    u64 r; asm("mul.rn.f32x2 %0, %1, %2;" : "=l"(r) : "l"(a), "l"(b)); return r;
}
__device__ __forceinline__ u64 fma2(u64 a, u64 b, u64 c) {
    u64 r; asm("fma.rn.f32x2 %0, %1, %2, %3;" : "=l"(r) : "l"(a), "l"(b), "l"(c)); return r;
}
__device__ __forceinline__ u64 add2(u64 a, u64 b) {
    u64 r; asm("add.rn.f32x2 %0, %1, %2;" : "=l"(r) : "l"(a), "l"(b)); return r;
}
__device__ __forceinline__ float frcp(float x) {
    float r; asm("rcp.approx.f32 %0, %1;" : "=f"(r) : "f"(x)); return r;
}

// exp(-k) for k in [1/6, 2/3): degree-5 poly about c=5/12. rel err ~4e-7.
// Scalar FFMA-imm form: rt=1 per SMSP, zero constant registers.
__device__ __forceinline__ float expnk(float k) {
    const float E = 0.6592406302004438f;         // exp(-5/12)
    float x = k - 0.4166666666666667f;
    float p = -E / 120.0f;
    p = fmaf(p, x,  E / 24.0f);
    p = fmaf(p, x, -E / 6.0f);
    p = fmaf(p, x,  E * 0.5f);
    p = fmaf(p, x, -E);
    p = fmaf(p, x,  E);
    return p;
}

// ============================================================================
// K1: warmup-based synaptic state + x_cat + input projection -> g_xw
// Block = 128 threads (4 warps) = one batch. Warp w owns t in [256w, 256w+256).
// Warp 0 starts from exact syn_x0; warps 1-3 warm up over the preceding 96
// steps from s=1 (contraction exp(-96/6) ~ 1e-7 kills the init error).
// Scalar FFMA-imm syn math (saves ~16 const registers -> 5 blocks/SM target);
// select-free XOR-permuted butterfly; lanes 0-7 store one xw h-pair each.
// ============================================================================
__global__ void __launch_bounds__(128, 5) k1_syn_proj(
    const float* __restrict__ inputs,   // [B,T,64]
    const float* __restrict__ syn_x0,   // [B,64]
    const float* __restrict__ w_ih,     // [128,16]
    float* __restrict__ out_xcat)       // [B,T,128]
{
    __shared__ float wsm[2*DD][HH];     // raw copy of w_ih

    const int b    = blockIdx.x;
    const int tid  = threadIdx.x;
    const int w    = tid >> 5;
    const int lane = tid & 31;
    const int t0   = w * CH;
    // slot permutation: sig(l^1)=sig^4, sig(l^2)=sig^2, sig(l^4)=sig^1
    const int sig  = ((lane & 1) << 2) | (lane & 2) | ((lane >> 2) & 1);

    {
        const float4* src = reinterpret_cast<const float4*>(w_ih);
        float4* dst = reinterpret_cast<float4*>(&wsm[0][0]);
        for (int i = tid; i < 2*DD*HH/4; i += 128) dst[i] = src[i];
    }
    __syncthreads();

    // slot i holds weights for h-pair p = i ^ sig
    u64 wa0[8], wa1[8], wb0[8], wb1[8];
#pragma unroll
    for (int i = 0; i < 8; i++) {
        const int p = i ^ sig;
        wa0[i] = *reinterpret_cast<const u64*>(&wsm[2*lane   ][2*p]);
        wa1[i] = *reinterpret_cast<const u64*>(&wsm[2*lane+1 ][2*p]);
        wb0[i] = *reinterpret_cast<const u64*>(&wsm[64+2*lane][2*p]);
        wb1[i] = *reinterpret_cast<const u64*>(&wsm[65+2*lane][2*p]);
    }

    // ---- synaptic state init ----
    u64 s2;
    if (w == 0) {
        float2 s0v = *reinterpret_cast<const float2*>(&syn_x0[b*DD + 2*lane]);
        s2 = pk2(s0v.x, s0v.y);
    } else {
        s2 = pk2(1.0f, 1.0f);
        const float2* wp = reinterpret_cast<const float2*>(inputs)
                           + ((size_t)b*TT + t0 - WU)*(DD/2) + lane;
        float2 wbuf[4];
#pragma unroll
        for (int k = 0; k < 4; k++) wbuf[k] = wp[k*(DD/2)];
#pragma unroll 4
        for (int t = 0; t < WU; t++) {
            float2 in = wbuf[t & 3];
            if (t + 4 < WU) wbuf[t & 3] = wp[(t + 4)*(DD/2)];
            float kx = fmaf(0.5f, in.x, INV_TAU);
            float ky = fmaf(0.5f, in.y, INV_TAU);
            float ex = expnk(kx);
            float ey = expnk(ky);
            float rx = frcp(kx) * INV_TAU;
            float ry = frcp(ky) * INV_TAU;
            float bx = fmaf(-rx, ex, rx);      // r(1-e)
            float by = fmaf(-ry, ey, ry);
            u64 e2 = pk2(ex, ey);
            u64 b2 = pk2(bx, by);
            s2 = fma2(e2, s2, b2);
        }
    }

    // ---- main loop: emit x_cat + xw ----
    const float2* ip = reinterpret_cast<const float2*>(inputs)
                       + ((size_t)b*TT + t0)*(DD/2) + lane;
    float2* xc = reinterpret_cast<float2*>(out_xcat)
                 + ((size_t)b*TT + t0)*DD + lane;
    float* xwp = g_xw + ((size_t)b*TT + t0)*HH;

    float2 buf[4];
#pragma unroll
    for (int k = 0; k < 4; k++) buf[k] = ip[k*(DD/2)];

#pragma unroll 4
    for (int t = 0; t < CH; t++) {
        float2 in = buf[t & 3];
        if (t + 4 < CH) buf[t & 3] = ip[(t + 4)*(DD/2)];

        // ---- syn: scalar FFMA-imm poly + rcp, packed state update ----
        float kx = fmaf(0.5f, in.x, INV_TAU);
        float ky = fmaf(0.5f, in.y, INV_TAU);
        float ex = expnk(kx);
        float ey = expnk(ky);
        float rx = frcp(kx) * INV_TAU;
        float ry = frcp(ky) * INV_TAU;

        u64 in64 = pk2(in.x, in.y);
        u64 sx2  = mul2(s2, in64);       // syn(pre-update) * input

        xc[t*DD] = in;                                        // x_cat[:, :64]
        *reinterpret_cast<u64*>(xc + t*DD + 32) = sx2;        // x_cat[:, 64:]

        float bx = fmaf(-rx, ex, rx);
        float by = fmaf(-ry, ey, ry);
        s2 = fma2(pk2(ex, ey), s2, pk2(bx, by));

        // ---- proj partials: slot i accumulates h-pair (i ^ sig) ----
        float sxx, sxy; unpk2(sx2, sxx, sxy);
        u64 dx0 = pk2(in.x, in.x);
        u64 dx1 = pk2(in.y, in.y);
        u64 ds0 = pk2(sxx, sxx);
        u64 ds1 = pk2(sxy, sxy);
        u64 acc[8];
#pragma unroll
        for (int i = 0; i < 8; i++) {
            u64 a = mul2(dx0, wa0[i]);
            a = fma2(dx1, wa1[i], a);
            a = fma2(ds0, wb0[i], a);
            a = fma2(ds1, wb1[i], a);
            acc[i] = a;
        }

        // ---- select-free butterfly: plain shfl_xor + add2 at every stage ----
#pragma unroll
        for (int i = 0; i < 4; i++)
            acc[i] = add2(acc[i], __shfl_xor_sync(0xffffffffu, acc[i + 4], 1));
#pragma unroll
        for (int i = 0; i < 2; i++)
            acc[i] = add2(acc[i], __shfl_xor_sync(0xffffffffu, acc[i + 2], 2));
        acc[0] = add2(acc[0], __shfl_xor_sync(0xffffffffu, acc[1], 4));
        acc[0] = add2(acc[0], __shfl_xor_sync(0xffffffffu, acc[0], 8));
        acc[0] = add2(acc[0], __shfl_xor_sync(0xffffffffu, acc[0], 16));

        // lane l (<8) holds complete h-pair sig(l): store u64 (coalesced 64B)
        if (lane < 8)
            *reinterpret_cast<u64*>(&xwp[t*HH + 2*sig]) = acc[0];
    }
}

// ============================================================================
// K2: sequential ReLU RNN + hidden + output. 2 batches per warp.
// Shuffle-free: h vector in double-buffered smem; per t = 1 STS + syncwarp +
// 4 LDS.128 broadcast; 4 short scalar-FMA chains. Output dot one step
// deferred (from the loaded h = h_{t-1}), epilogue for the final step.
// ============================================================================
__global__ void __launch_bounds__(32) k2_rnn(
    const float* __restrict__ h0,       // [B,16]
    const float* __restrict__ w_hh,     // [16,16]
    const float* __restrict__ bias,     // [16]
    const float* __restrict__ lin_w,    // [16]
    const float* __restrict__ lin_b,    // [1]
    float* __restrict__ out_output,     // [B,T]
    float* __restrict__ out_hidden)     // [B,T,16]
{
    __shared__ float hbuf[2][2][HH];    // [parity][batch-half][h]

    const int lane = threadIdx.x;
    const int j    = lane & 15;
    const int hf   = lane >> 4;
    const int b    = blockIdx.x * 2 + hf;

    float wj[HH], lw[HH];
#pragma unroll
    for (int i = 0; i < HH; i++) {
        wj[i] = w_hh[i*HH + j];
        lw[i] = lin_w[i];
    }
    const float biasj = bias[j];
    const float lb    = lin_b[0];

    hbuf[0][hf][j] = h0[b*HH + j];

    const float* xp = g_xw + (size_t)b*TT*HH + j;
    float*      hid = out_hidden + (size_t)b*TT*HH + j;
    float*       op = out_output + (size_t)b*TT;

    float buf[8];
#pragma unroll
    for (int p = 0; p < 8; p++) buf[p] = xp[p*HH];

#pragma unroll 8
    for (int t = 0; t < TT; t++) {
        float xwv = buf[t & 7];
        if (t + 8 < TT) buf[t & 7] = xp[(t + 8)*HH];

        __syncwarp();
        const int pr = t & 1;
        // h_{t-1}: 4x LDS.128 broadcast (conflict-free)
        float4 A = *reinterpret_cast<const float4*>(&hbuf[pr][hf][0]);
        float4 Bq = *reinterpret_cast<const float4*>(&hbuf[pr][hf][4]);
        float4 C = *reinterpret_cast<const float4*>(&hbuf[pr][hf][8]);
        float4 Dq = *reinterpret_cast<const float4*>(&hbuf[pr][hf][12]);

        // matvec for column j: 4 chains of depth 4
        float a0 = xwv + biasj, a1 = 0.0f, a2 = 0.0f, a3 = 0.0f;
        a0 = fmaf(A.x,  wj[0],  a0);  a1 = fmaf(A.y,  wj[1],  a1);
        a2 = fmaf(A.z,  wj[2],  a2);  a3 = fmaf(A.w,  wj[3],  a3);
        a0 = fmaf(Bq.x, wj[4],  a0);  a1 = fmaf(Bq.y, wj[5],  a1);
        a2 = fmaf(Bq.z, wj[6],  a2);  a3 = fmaf(Bq.w, wj[7],  a3);
        a0 = fmaf(C.x,  wj[8],  a0);  a1 = fmaf(C.y,  wj[9],  a1);
        a2 = fmaf(C.z,  wj[10], a2);  a3 = fmaf(C.w,  wj[11], a3);
        a0 = fmaf(Dq.x, wj[12], a0);  a1 = fmaf(Dq.y, wj[13], a1);
        a2 = fmaf(Dq.z, wj[14], a2);  a3 = fmaf(Dq.w, wj[15], a3);
        float h = fmaxf((a0 + a1) + (a2 + a3), 0.0f);

        hid[t*HH] = h;
        hbuf[pr ^ 1][hf][j] = h;

        // output for step t-1 from A..D (= h_{t-1}); every lane computes
        float v0 = A.x*lw[0] + A.y*lw[1];
        float v1 = A.z*lw[2] + A.w*lw[3];
        v0 = fmaf(Bq.x, lw[4],  v0);  v1 = fmaf(Bq.y, lw[5],  v1);
        v0 = fmaf(Bq.z, lw[6],  v0);  v1 = fmaf(Bq.w, lw[7],  v1);
        v0 = fmaf(C.x,  lw[8],  v0);  v1 = fmaf(C.y,  lw[9],  v1);
        v0 = fmaf(C.z,  lw[10], v0);  v1 = fmaf(C.w,  lw[11], v1);
        v0 = fmaf(Dq.x, lw[12], v0);  v1 = fmaf(Dq.y, lw[13], v1);
        v0 = fmaf(Dq.z, lw[14], v0);  v1 = fmaf(Dq.w, lw[15], v1);
        if (j == 0 && t > 0) op[t - 1] = v0 + v1 + lb;
    }

    // epilogue: output for t = TT-1 (last write went to parity 0)
    __syncwarp();
    {
        float4 A = *reinterpret_cast<const float4*>(&hbuf[0][hf][0]);
        float4 Bq = *reinterpret_cast<const float4*>(&hbuf[0][hf][4]);
        float4 C = *reinterpret_cast<const float4*>(&hbuf[0][hf][8]);
        float4 Dq = *reinterpret_cast<const float4*>(&hbuf[0][hf][12]);
        float v0 = A.x*lw[0] + A.y*lw[1];
        float v1 = A.z*lw[2] + A.w*lw[3];
        v0 = fmaf(Bq.x, lw[4],  v0);  v1 = fmaf(Bq.y, lw[5],  v1);
        v0 = fmaf(Bq.z, lw[6],  v0);  v1 = fmaf(Bq.w, lw[7],  v1);
        v0 = fmaf(C.x,  lw[8],  v0);  v1 = fmaf(C.y,  lw[9],  v1);
        v0 = fmaf(C.z,  lw[10], v0);  v1 = fmaf(C.w,  lw[11], v1);
        v0 = fmaf(Dq.x, lw[12], v0);  v1 = fmaf(Dq.y, lw[13], v1);
        v0 = fmaf(Dq.z, lw[14], v0);  v1 = fmaf(Dq.w, lw[15], v1);
        if (j == 0) op[TT - 1] = v0 + v1 + lb;
    }
}

extern "C" void kernel_launch(void* const* d_in, const int* in_sizes, int n_in,
                              void* d_out, int out_size) {
    const float* inputs = (const float*)d_in[0];   // [B,T,64]
    const float* syn_x0 = (const float*)d_in[1];   // [B,64]
    const float* h0     = (const float*)d_in[2];   // [B,16]
    const float* w_ih   = (const float*)d_in[3];   // [128,16]
    const float* w_hh   = (const float*)d_in[4];   // [16,16]
    const float* bias   = (const float*)d_in[5];   // [16]
    const float* lin_w  = (const float*)d_in[6];   // [16,1]
    const float* lin_b  = (const float*)d_in[7];   // [1]

    float* out = (float*)d_out;
    // tuple concat order: output [B,T,1], hidden [B,T,16], x_cat [B,T,128]
    float* out_output = out;
    float* out_hidden = out + (size_t)BB*TT;
    float* out_xcat   = out + (size_t)BB*TT + (size_t)BB*TT*HH;

    k1_syn_proj<<<BB, 128>>>(inputs, syn_x0, w_ih, out_xcat);
    k2_rnn<<<BB/2, 32>>>(h0, w_hh, bias, lin_w, lin_b, out_output, out_hidden);
}

// round 17
// speedup vs baseline: 1.0413x; 1.0413x over previous
#include <cuda_runtime.h>

#define BB 2048
#define TT 1024
#define DD 64
#define HH 16
#define CH 256             // timesteps per K1 warp (4 warps per batch)
#define WU 96              // warmup steps: decay exp(-96/6) ~ 1.1e-7
#define INV_TAU (1.0f/6.0f)

typedef unsigned long long u64;

// xw scratch: [B, T, 16]
__device__ float g_xw[(size_t)BB * TT * HH];

__device__ __forceinline__ u64 pk2(float lo, float hi) {
    u64 r; asm("mov.b64 %0, {%1,%2};" : "=l"(r) : "f"(lo), "f"(hi)); return r;
}
__device__ __forceinline__ void unpk2(u64 a, float& lo, float& hi) {
    asm("mov.b64 {%0,%1}, %2;" : "=f"(lo), "=f"(hi) : "l"(a));
}
__device__ __forceinline__ u64 mul2(u64 a, u64 b) {
    u64 r; asm("mul.rn.f32x2 %0, %1, %2;" : "=l"(r) : "l"(a), "l"(b)); return r;
}
__device__ __forceinline__ u64 fma2(u64 a, u64 b, u64 c) {
    u64 r; asm("fma.rn.f32x2 %0, %1, %2, %3;" : "=l"(r) : "l"(a), "l"(b), "l"(c)); return r;
}
__device__ __forceinline__ u64 add2(u64 a, u64 b) {
    u64 r; asm("add.rn.f32x2 %0, %1, %2;" : "=l"(r) : "l"(a), "l"(b)); return r;
}
__device__ __forceinline__ u64 sub2(u64 a, u64 b) {
    u64 r; asm("sub.rn.f32x2 %0, %1, %2;" : "=l"(r) : "l"(a), "l"(b)); return r;
}
__device__ __forceinline__ float frcp(float x) {
    float r; asm("rcp.approx.f32 %0, %1;" : "=f"(r) : "f"(x)); return r;
}

// exp(-5/12) for the centered degree-5 exp(-k) poly (k in [1/6, 2/3), err ~4e-7)
#define EXPC 0.6592406302004438f

// ============================================================================
// K1: warmup-based synaptic state + x_cat + input projection -> g_xw
// (exact R15 version — benched 397us)
// Block = 128 threads (4 warps) = one batch. Warp w owns t in [256w, 256w+256).
// Warp 0 starts from exact syn_x0; warps 1-3 warm up over the preceding 96
// steps from s=1 (contraction exp(-96/6) ~ 1e-7 kills the init error).
// ============================================================================
__global__ void __launch_bounds__(128, 4) k1_syn_proj(
    const float* __restrict__ inputs,   // [B,T,64]
    const float* __restrict__ syn_x0,   // [B,64]
    const float* __restrict__ w_ih,     // [128,16]
    float* __restrict__ out_xcat)       // [B,T,128]
{
    __shared__ float wsm[2*DD][HH];     // raw copy of w_ih

    const int b    = blockIdx.x;
    const int tid  = threadIdx.x;
    const int w    = tid >> 5;
    const int lane = tid & 31;
    const int t0   = w * CH;
    // slot permutation: sig(l^1)=sig^4, sig(l^2)=sig^2, sig(l^4)=sig^1
    const int sig  = ((lane & 1) << 2) | (lane & 2) | ((lane >> 2) & 1);

    {
        const float4* src = reinterpret_cast<const float4*>(w_ih);
        float4* dst = reinterpret_cast<float4*>(&wsm[0][0]);
        for (int i = tid; i < 2*DD*HH/4; i += 128) dst[i] = src[i];
    }
    __syncthreads();

    // slot i holds weights for h-pair p = i ^ sig
    u64 wa0[8], wa1[8], wb0[8], wb1[8];
#pragma unroll
    for (int i = 0; i < 8; i++) {
        const int p = i ^ sig;
        wa0[i] = *reinterpret_cast<const u64*>(&wsm[2*lane   ][2*p]);
        wa1[i] = *reinterpret_cast<const u64*>(&wsm[2*lane+1 ][2*p]);
        wb0[i] = *reinterpret_cast<const u64*>(&wsm[64+2*lane][2*p]);
        wb1[i] = *reinterpret_cast<const u64*>(&wsm[65+2*lane][2*p]);
    }

    // packed constants
    const u64 HALF2 = pk2(0.5f, 0.5f);
    const u64 TAU2  = pk2(INV_TAU, INV_TAU);
    const u64 CTR2  = pk2(0.4166666666666667f, 0.4166666666666667f);
    const u64 P5 = pk2(-EXPC/120.0f, -EXPC/120.0f);
    const u64 P4 = pk2( EXPC/24.0f,   EXPC/24.0f);
    const u64 P3 = pk2(-EXPC/6.0f,   -EXPC/6.0f);
    const u64 P2 = pk2( EXPC*0.5f,    EXPC*0.5f);
    const u64 P1 = pk2(-EXPC,        -EXPC);
    const u64 P0 = pk2( EXPC,         EXPC);

    // ---- synaptic state init ----
    u64 s2;
    if (w == 0) {
        float2 s0v = *reinterpret_cast<const float2*>(&syn_x0[b*DD + 2*lane]);
        s2 = pk2(s0v.x, s0v.y);
    } else {
        s2 = pk2(1.0f, 1.0f);
        const float2* wp = reinterpret_cast<const float2*>(inputs)
                           + ((size_t)b*TT + t0 - WU)*(DD/2) + lane;
        float2 wbuf[4];
#pragma unroll
        for (int k = 0; k < 4; k++) wbuf[k] = wp[k*(DD/2)];
#pragma unroll 4
        for (int t = 0; t < WU; t++) {
            float2 in = wbuf[t & 3];
            if (t + 4 < WU) wbuf[t & 3] = wp[(t + 4)*(DD/2)];
            u64 in64 = pk2(in.x, in.y);
            u64 k2 = fma2(in64, HALF2, TAU2);
            u64 x2 = sub2(k2, CTR2);
            u64 e2 = fma2(P5, x2, P4);
            e2 = fma2(e2, x2, P3);
            e2 = fma2(e2, x2, P2);
            e2 = fma2(e2, x2, P1);
            e2 = fma2(e2, x2, P0);
            float kx, ky; unpk2(k2, kx, ky);
            u64 r2 = mul2(pk2(frcp(kx), frcp(ky)), TAU2);
            u64 b2 = sub2(r2, mul2(r2, e2));
            s2 = fma2(e2, s2, b2);
        }
    }

    // ---- main loop: emit x_cat + xw ----
    const float2* ip = reinterpret_cast<const float2*>(inputs)
                       + ((size_t)b*TT + t0)*(DD/2) + lane;
    float2* xc = reinterpret_cast<float2*>(out_xcat)
                 + ((size_t)b*TT + t0)*DD + lane;
    float* xwp = g_xw + ((size_t)b*TT + t0)*HH;

    float2 buf[4];
#pragma unroll
    for (int k = 0; k < 4; k++) buf[k] = ip[k*(DD/2)];

#pragma unroll 4
    for (int t = 0; t < CH; t++) {
        float2 in = buf[t & 3];
        if (t + 4 < CH) buf[t & 3] = ip[(t + 4)*(DD/2)];

        // ---- packed syn: e = poly(k), r = tau/k, sx = s*in, s' = e*s + r(1-e)
        u64 in64 = pk2(in.x, in.y);
        u64 k2 = fma2(in64, HALF2, TAU2);
        u64 x2 = sub2(k2, CTR2);
        u64 e2 = fma2(P5, x2, P4);
        e2 = fma2(e2, x2, P3);
        e2 = fma2(e2, x2, P2);
        e2 = fma2(e2, x2, P1);
        e2 = fma2(e2, x2, P0);
        float kx, ky; unpk2(k2, kx, ky);
        u64 r2 = mul2(pk2(frcp(kx), frcp(ky)), TAU2);

        u64 sx2 = mul2(s2, in64);        // syn(pre-update) * input

        xc[t*DD] = in;                                        // x_cat[:, :64]
        *reinterpret_cast<u64*>(xc + t*DD + 32) = sx2;        // x_cat[:, 64:]

        u64 b2 = sub2(r2, mul2(r2, e2));
        s2 = fma2(e2, s2, b2);

        // ---- proj partials: slot i accumulates h-pair (i ^ sig) ----
        float sxx, sxy; unpk2(sx2, sxx, sxy);
        u64 dx0 = pk2(in.x, in.x);
        u64 dx1 = pk2(in.y, in.y);
        u64 ds0 = pk2(sxx, sxx);
        u64 ds1 = pk2(sxy, sxy);
        u64 acc[8];
#pragma unroll
        for (int i = 0; i < 8; i++) {
            u64 a = mul2(dx0, wa0[i]);
            a = fma2(dx1, wa1[i], a);
            a = fma2(ds0, wb0[i], a);
            a = fma2(ds1, wb1[i], a);
            acc[i] = a;
        }

        // ---- select-free butterfly: plain shfl_xor + add2 at every stage ----
#pragma unroll
        for (int i = 0; i < 4; i++)
            acc[i] = add2(acc[i], __shfl_xor_sync(0xffffffffu, acc[i + 4], 1));
#pragma unroll
        for (int i = 0; i < 2; i++)
            acc[i] = add2(acc[i], __shfl_xor_sync(0xffffffffu, acc[i + 2], 2));
        acc[0] = add2(acc[0], __shfl_xor_sync(0xffffffffu, acc[1], 4));
        acc[0] = add2(acc[0], __shfl_xor_sync(0xffffffffu, acc[0], 8));
        acc[0] = add2(acc[0], __shfl_xor_sync(0xffffffffu, acc[0], 16));

        // lane l (<8) holds complete h-pair sig(l): store u64 (coalesced 64B)
        if (lane < 8)
            *reinterpret_cast<u64*>(&xwp[t*HH + 2*sig]) = acc[0];
    }
}

// ============================================================================
// K2: sequential ReLU RNN + hidden + output. 4 batches per warp.
// Lane = (batch bb = lane>>3, h-pair jp = lane&7 owning h[2jp], h[2jp+1]).
// 16 per-lane-src shfl/t serve all 4 batches (4 shfl/batch-t). All global
// accesses 64-bit, coalesced per batch row. Output dot one step deferred.
// ============================================================================
__global__ void __launch_bounds__(32) k2_rnn(
    const float* __restrict__ h0,       // [B,16]
    const float* __restrict__ w_hh,     // [16,16]
    const float* __restrict__ bias,     // [16]
    const float* __restrict__ lin_w,    // [16]
    const float* __restrict__ lin_b,    // [1]
    float* __restrict__ out_output,     // [B,T]
    float* __restrict__ out_hidden)     // [B,T,16]
{
    const int lane = threadIdx.x;
    const int jp   = lane & 7;           // h-pair index
    const int bb   = lane >> 3;          // batch within warp
    const int base = bb * 8;             // src lane base for broadcasts
    const int b    = blockIdx.x * 4 + bb;

    // columns 2jp, 2jp+1 of W_hh + lin weights
    float wlo[HH], whi[HH], lw[HH];
#pragma unroll
    for (int i = 0; i < HH; i++) {
        wlo[i] = w_hh[i*HH + 2*jp];
        whi[i] = w_hh[i*HH + 2*jp + 1];
        lw[i]  = lin_w[i];
    }
    const float b_lo = bias[2*jp];
    const float b_hi = bias[2*jp + 1];
    const float lb   = lin_b[0];

    float2 h2 = *reinterpret_cast<const float2*>(&h0[b*HH + 2*jp]);
    float hlo = h2.x, hhi = h2.y;

    const float2* xp = reinterpret_cast<const float2*>(g_xw + (size_t)b*TT*HH) + jp;
    float2*      hid = reinterpret_cast<float2*>(out_hidden + (size_t)b*TT*HH) + jp;
    float*        op = out_output + (size_t)b*TT;

    float2 buf[8];
#pragma unroll
    for (int p = 0; p < 8; p++) buf[p] = xp[p*(HH/2)];

#pragma unroll 8
    for (int t = 0; t < TT; t++) {
        float2 xw2 = buf[t & 7];
        if (t + 8 < TT) buf[t & 7] = xp[(t + 8)*(HH/2)];

        // broadcast h_{t-1} of own batch: src = base + i/2, lo/hi by i&1
        float hb[HH];
#pragma unroll
        for (int i = 0; i < HH; i += 2) {
            hb[i]     = __shfl_sync(0xffffffffu, hlo, base + (i >> 1));
            hb[i + 1] = __shfl_sync(0xffffffffu, hhi, base + (i >> 1));
        }

        // matvec for columns 2jp, 2jp+1: 4 independent chains of depth 8
        float a0 = xw2.x + b_lo, a1 = 0.0f;
        float a2 = xw2.y + b_hi, a3 = 0.0f;
#pragma unroll
        for (int i = 0; i < HH; i += 2) {
            a0 = fmaf(hb[i],     wlo[i],     a0);
            a1 = fmaf(hb[i + 1], wlo[i + 1], a1);
            a2 = fmaf(hb[i],     whi[i],     a2);
            a3 = fmaf(hb[i + 1], whi[i + 1], a3);
        }
        hlo = fmaxf(a0 + a1, 0.0f);
        hhi = fmaxf(a2 + a3, 0.0f);

        hid[t*(HH/2)] = make_float2(hlo, hhi);   // 8 lanes x 8B = 64B per batch

        // output for step t-1 from hb (= h_{t-1}); deferred, off-chain
        float v0 = 0.0f, v1 = 0.0f;
#pragma unroll
        for (int i = 0; i < HH; i += 2) {
            v0 = fmaf(hb[i],     lw[i],     v0);
            v1 = fmaf(hb[i + 1], lw[i + 1], v1);
        }
        if (jp == 0 && t > 0) op[t - 1] = v0 + v1 + lb;
    }

    // epilogue: output for t = TT-1
    {
        float hb[HH];
#pragma unroll
        for (int i = 0; i < HH; i += 2) {
            hb[i]     = __shfl_sync(0xffffffffu, hlo, base + (i >> 1));
            hb[i + 1] = __shfl_sync(0xffffffffu, hhi, base + (i >> 1));
        }
        float v0 = 0.0f, v1 = 0.0f;
#pragma unroll
        for (int i = 0; i < HH; i += 2) {
            v0 = fmaf(hb[i],     lw[i],     v0);
            v1 = fmaf(hb[i + 1], lw[i + 1], v1);
        }
        if (jp == 0) op[TT - 1] = v0 + v1 + lb;
    }
}

extern "C" void kernel_launch(void* const* d_in, const int* in_sizes, int n_in,
                              void* d_out, int out_size) {
    const float* inputs = (const float*)d_in[0];   // [B,T,64]
    const float* syn_x0 = (const float*)d_in[1];   // [B,64]
    const float* h0     = (const float*)d_in[2];   // [B,16]
    const float* w_ih   = (const float*)d_in[3];   // [128,16]
    const float* w_hh   = (const float*)d_in[4];   // [16,16]
    const float* bias   = (const float*)d_in[5];   // [16]
    const float* lin_w  = (const float*)d_in[6];   // [16,1]
    const float* lin_b  = (const float*)d_in[7];   // [1]

    float* out = (float*)d_out;
    // tuple concat order: output [B,T,1], hidden [B,T,16], x_cat [B,T,128]
    float* out_output = out;
    float* out_hidden = out + (size_t)BB*TT;
    float* out_xcat   = out + (size_t)BB*TT + (size_t)BB*TT*HH;

    k1_syn_proj<<<BB, 128>>>(inputs, syn_x0, w_ih, out_xcat);
    k2_rnn<<<BB/4, 32>>>(h0, w_hh, bias, lin_w, lin_b, out_output, out_hidden);
}